// round 8
// baseline (speedup 1.0000x reference)
#include <cuda_runtime.h>
#include <cuda_bf16.h>
#include <cstdint>

#define NN 20000

// ---------------- device scratch ----------------
__device__ float g_z1 [NN * 64];
__device__ float g_hd1[NN * 64];
__device__ float g_zc [NN * 64];
__device__ float g_u  [NN * 64];

// ---------------- generic helpers ----------------
__device__ __forceinline__ float warpSumAll(float v) {
#pragma unroll
    for (int o = 16; o > 0; o >>= 1) v += __shfl_xor_sync(0xffffffffu, v, o);
    return v;
}
__device__ __forceinline__ float warpMaxAll(float v) {
#pragma unroll
    for (int o = 16; o > 0; o >>= 1) v = fmaxf(v, __shfl_xor_sync(0xffffffffu, v, o));
    return v;
}
__device__ __forceinline__ float lrelu(float x) { return x > 0.f ? x : 0.01f * x; }
__device__ __forceinline__ float eluf(float x) {
    if (x > 0.f) return x;
    if (x > -0.25f)
        return x * (1.f + x * (0.5f + x * (0.16666667f + x * 0.041666667f)));
    return __expf(x) - 1.f;
}

// ---------------- mma.sync m16n8k16 bf16 (sm_80+ PTX, assembles for sm_103) ----------------
__device__ __forceinline__ void mma16816(float* c, const uint32_t* a, const uint32_t* b) {
    asm volatile(
        "mma.sync.aligned.m16n8k16.row.col.f32.bf16.bf16.f32 "
        "{%0,%1,%2,%3}, {%4,%5,%6,%7}, {%8,%9}, {%0,%1,%2,%3};"
        : "+f"(c[0]), "+f"(c[1]), "+f"(c[2]), "+f"(c[3])
        : "r"(a[0]), "r"(a[1]), "r"(a[2]), "r"(a[3]), "r"(b[0]), "r"(b[1]));
}
__device__ __forceinline__ uint32_t lds32(const __nv_bfloat16* p) {
    return *(const uint32_t*)p;
}

// =====================================================================
// Tensor GEMM tile: 128 nodes x 128 out, K=128, bf16 hi/lo 3-term split.
// DEC=0: C = h @ [fcE;dfE]^T  -> g_z1 (cols 0-63), g_hd1 (cols 64-127)
// DEC=1: C = [zc|u] @ [fcD|diffD]^T -> Oout[node*128+col]
// smem pitch = 136 bf16 (68 words): fragment LDS.32 loads are conflict-free
// (bank = 4*row + kword, all 32 distinct).
// =====================================================================
static constexpr int PITCH = 136;
static constexpr int TBUF  = 128 * PITCH;               // bf16 elems per buffer
static constexpr int GSMEM = 4 * TBUF * 2;              // bytes = 139264

template <int DEC>
__global__ __launch_bounds__(256, 1)
void gemm_tc(const float* __restrict__ Ain, const float* __restrict__ W0,
             const float* __restrict__ W1, float* __restrict__ Oout) {
    extern __shared__ __nv_bfloat16 smbf[];
    __nv_bfloat16* Ah = smbf;
    __nv_bfloat16* Al = smbf + TBUF;
    __nv_bfloat16* Bh = smbf + 2 * TBUF;
    __nv_bfloat16* Bl = smbf + 3 * TBUF;

    const int t = threadIdx.x, lane = t & 31, wid = t >> 5;
    const int node0 = blockIdx.x * 128;

    // ---- stage: fp32 -> bf16 hi/lo for A (nodes) and B (weights, n-major) ----
    for (int idx = t; idx < 128 * 128; idx += 256) {
        const int row = idx >> 7, col = idx & 127;
        const int node = node0 + row;
        float av;
        if (DEC) av = (node < NN) ? ((col < 64) ? g_zc[node * 64 + col]
                                               : g_u [node * 64 + col - 64]) : 0.f;
        else     av = (node < NN) ? Ain[node * 128 + col] : 0.f;
        const __nv_bfloat16 ah = __float2bfloat16(av);
        Ah[row * PITCH + col] = ah;
        Al[row * PITCH + col] = __float2bfloat16(av - __bfloat162float(ah));

        float wv;                       // row = output dim n, col = k
        if (DEC) wv = (col < 64) ? W0[row * 64 + col] : W1[row * 64 + col - 64];
        else     wv = (row < 64) ? W0[row * 128 + col] : W1[(row - 64) * 128 + col];
        const __nv_bfloat16 bh = __float2bfloat16(wv);
        Bh[row * PITCH + col] = bh;
        Bl[row * PITCH + col] = __float2bfloat16(wv - __bfloat162float(bh));
    }
    __syncthreads();

    // ---- warp tiling: 4 warps in M x 2 in N; warp tile 32x64 ----
    const int wm = wid & 3, wn = wid >> 2;
    const int mrow0 = wm * 32, ncol0 = wn * 64;
    const int qr = lane >> 2, qc = lane & 3;

    float acc[2][8][4];
#pragma unroll
    for (int mi = 0; mi < 2; mi++)
#pragma unroll
        for (int ni = 0; ni < 8; ni++)
#pragma unroll
            for (int x = 0; x < 4; x++) acc[mi][ni][x] = 0.f;

#pragma unroll
    for (int kb = 0; kb < 8; kb++) {
        const int k0 = kb * 16 + qc * 2;

        uint32_t aH[2][4], aL[2][4];
#pragma unroll
        for (int mi = 0; mi < 2; mi++) {
            const int base = (mrow0 + mi * 16 + qr) * PITCH + k0;
            aH[mi][0] = lds32(Ah + base);
            aH[mi][1] = lds32(Ah + base + 8 * PITCH);
            aH[mi][2] = lds32(Ah + base + 8);
            aH[mi][3] = lds32(Ah + base + 8 * PITCH + 8);
            aL[mi][0] = lds32(Al + base);
            aL[mi][1] = lds32(Al + base + 8 * PITCH);
            aL[mi][2] = lds32(Al + base + 8);
            aL[mi][3] = lds32(Al + base + 8 * PITCH + 8);
        }

#pragma unroll
        for (int ni = 0; ni < 8; ni++) {
            const int base = (ncol0 + ni * 8 + qr) * PITCH + k0;
            uint32_t bH[2], bL[2];
            bH[0] = lds32(Bh + base);  bH[1] = lds32(Bh + base + 8);
            bL[0] = lds32(Bl + base);  bL[1] = lds32(Bl + base + 8);
#pragma unroll
            for (int mi = 0; mi < 2; mi++) {
                mma16816(acc[mi][ni], aH[mi], bH);
                mma16816(acc[mi][ni], aH[mi], bL);
                mma16816(acc[mi][ni], aL[mi], bH);
            }
        }
    }

    // ---- epilogue: registers -> gmem ----
#pragma unroll
    for (int mi = 0; mi < 2; mi++) {
        const int node_a = node0 + mrow0 + mi * 16 + qr;
        const int node_b = node_a + 8;
#pragma unroll
        for (int ni = 0; ni < 8; ni++) {
            const int c0 = ncol0 + ni * 8 + qc * 2;
            const float2 va = make_float2(acc[mi][ni][0], acc[mi][ni][1]);
            const float2 vb = make_float2(acc[mi][ni][2], acc[mi][ni][3]);
            if (DEC) {
                if (node_a < NN) *(float2*)(Oout + node_a * 128 + c0) = va;
                if (node_b < NN) *(float2*)(Oout + node_b * 128 + c0) = vb;
            } else {
                float* dst = (c0 < 64) ? g_z1 : g_hd1;
                const int cc = c0 & 63;
                if (node_a < NN) *(float2*)(dst + node_a * 64 + cc) = va;
                if (node_b < NN) *(float2*)(dst + node_b * 64 + cc) = vb;
            }
        }
    }
}

// ---------------- encoder aggregation: 3 hops + hop-attention combine ----------------
__global__ __launch_bounds__(256) void enc_agg(const float* __restrict__ attE,
                                               const float* __restrict__ attC) {
    __shared__ __align__(16) float hdT[56][66];
    __shared__ float sT[56];
    __shared__ __align__(16) float wS[3][25][36];
    __shared__ float sAe[64], sAc[64];

    const int t = threadIdx.x, w = t >> 5, lane = t & 31;
    const int nodeBase = blockIdx.x * 32;
    const int nl0 = w * 4;

    if (t < 64) { sAe[t] = attE[t]; sAc[t] = attC[t]; }

    for (int r = w; r < 56; r += 8) {
        int g = nodeBase - 24 + r;
        if (g < 0) g += NN;
        ((float2*)hdT[r])[lane] = ((const float2*)(g_hd1 + g * 64))[lane];
    }
    __syncthreads();

    for (int r = w; r < 56; r += 8) {
        float2 hv = ((float2*)hdT[r])[lane];
        float p = warpSumAll(hv.x * sAe[2 * lane] + hv.y * sAe[2 * lane + 1]);
        if (lane == 0) sT[r] = p;
    }
    __syncthreads();

#pragma unroll
    for (int j = 0; j < 4; j++) {
        const int li = 24 + nl0 + j;
        const float s_i = sT[li];
        float el = (lane < 25) ? lrelu(sT[li - lane] - s_i) : -1e30f;
        const float m1 = warpMaxAll(lane < 9  ? el : -1e30f);
        const float m2 = warpMaxAll(lane < 17 ? el : -1e30f);
        const float m3 = warpMaxAll(el);
        const float ex1 = (lane < 9)  ? __expf(el - m1) : 0.f;
        const float ex2 = (lane < 17) ? __expf(el - m2) : 0.f;
        const float ex3 = (lane < 25) ? __expf(el - m3) : 0.f;
        const float r1 = 1.f / warpSumAll(ex1);
        const float r2 = 1.f / warpSumAll(ex2);
        const float r3 = 1.f / warpSumAll(ex3);
        if (lane < 25) {
            wS[0][lane][nl0 + j] = ex1 * r1;
            wS[1][lane][nl0 + j] = ex2 * r2;
            wS[2][lane][nl0 + j] = ex3 * r3;
        }
    }
    __syncwarp();

    float2 A[4][3];
#pragma unroll
    for (int j = 0; j < 4; j++)
#pragma unroll
        for (int hh = 0; hh < 3; hh++) A[j][hh] = make_float2(0.f, 0.f);

#pragma unroll
    for (int tt = 0; tt < 25; tt++) {
        const float4 w3 = *(const float4*)&wS[2][tt][nl0];
        float4 w2, w1;
        if (tt < 17) w2 = *(const float4*)&wS[1][tt][nl0];
        if (tt < 9)  w1 = *(const float4*)&wS[0][tt][nl0];
#pragma unroll
        for (int j = 0; j < 4; j++) {
            const float2 hv = ((float2*)hdT[24 + nl0 + j - tt])[lane];
            const float g3 = ((const float*)&w3)[j];
            A[j][2].x = fmaf(g3, hv.x, A[j][2].x);
            A[j][2].y = fmaf(g3, hv.y, A[j][2].y);
            if (tt < 17) {
                const float g2 = ((const float*)&w2)[j];
                A[j][1].x = fmaf(g2, hv.x, A[j][1].x);
                A[j][1].y = fmaf(g2, hv.y, A[j][1].y);
            }
            if (tt < 9) {
                const float g1 = ((const float*)&w1)[j];
                A[j][0].x = fmaf(g1, hv.x, A[j][0].x);
                A[j][0].y = fmaf(g1, hv.y, A[j][0].y);
            }
        }
    }

    const float ac0 = sAc[2 * lane], ac1 = sAc[2 * lane + 1];
#pragma unroll
    for (int j = 0; j < 4; j++) {
        const int li = 24 + nl0 + j;
        const int node = nodeBase + nl0 + j;
        const float2 hvi = ((float2*)hdT[li])[lane];
        const float2 zv  = ((const float2*)(g_z1 + node * 64))[lane];
        float2 Z1, Z2, Z3;
        Z1.x = eluf(zv.x + A[j][0].x - hvi.x); Z1.y = eluf(zv.y + A[j][0].y - hvi.y);
        Z2.x = eluf(zv.x + A[j][1].x - hvi.x); Z2.y = eluf(zv.y + A[j][1].y - hvi.y);
        Z3.x = eluf(zv.x + A[j][2].x - hvi.x); Z3.y = eluf(zv.y + A[j][2].y - hvi.y);

        const float c1 = warpSumAll(Z1.x * ac0 + Z1.y * ac1);
        const float c2 = warpSumAll(Z2.x * ac0 + Z2.y * ac1);
        const float c3 = warpSumAll(Z3.x * ac0 + Z3.y * ac1);
        const float l1 = lrelu(c1), l2 = lrelu(c2), l3 = lrelu(c3);
        const float mx = fmaxf(l1, fmaxf(l2, l3));
        const float e1 = __expf(l1 - mx), e2 = __expf(l2 - mx), e3 = __expf(l3 - mx);
        const float rd = 1.f / (e1 + e2 + e3);

        float2 o;
        o.x = (e1 * Z1.x + e2 * Z2.x + e3 * Z3.x) * rd;
        o.y = (e1 * Z1.y + e2 * Z2.y + e3 * Z3.y) * rd;
        ((float2*)(g_zc + node * 64))[lane] = o;
    }
}

// ---------------- decoder aggregation in 64-dim latent ----------------
__global__ __launch_bounds__(256) void dec_agg(const float* __restrict__ diffD,
                                               const float* __restrict__ attD) {
    __shared__ __align__(16) float zT[56][66];
    __shared__ float sT[56];
    __shared__ __align__(16) float wS[25][36];
    __shared__ float sv[64];

    const int t = threadIdx.x, w = t >> 5, lane = t & 31;
    const int nodeBase = blockIdx.x * 32;
    const int nl0 = w * 4;

    if (t < 64) {
        float a = 0.f;
#pragma unroll 4
        for (int od = 0; od < 128; od++) a = fmaf(diffD[od * 64 + t], attD[od], a);
        sv[t] = a;
    }

    for (int r = w; r < 56; r += 8) {
        int g = nodeBase - 24 + r;
        if (g < 0) g += NN;
        ((float2*)zT[r])[lane] = ((const float2*)(g_zc + g * 64))[lane];
    }
    __syncthreads();

    for (int r = w; r < 56; r += 8) {
        float2 zv = ((float2*)zT[r])[lane];
        float p = warpSumAll(zv.x * sv[2 * lane] + zv.y * sv[2 * lane + 1]);
        if (lane == 0) sT[r] = p;
    }
    __syncthreads();

#pragma unroll
    for (int j = 0; j < 4; j++) {
        const int li = 24 + nl0 + j;
        const float s_i = sT[li];
        float el = (lane < 25) ? lrelu(sT[li - lane] - s_i) : -1e30f;
        const float m = warpMaxAll(el);
        const float ex = (lane < 25) ? __expf(el - m) : 0.f;
        const float rd = 1.f / warpSumAll(ex);
        if (lane < 25) wS[lane][nl0 + j] = ex * rd;
    }
    __syncwarp();

    float2 A[4];
#pragma unroll
    for (int j = 0; j < 4; j++) A[j] = make_float2(0.f, 0.f);

#pragma unroll
    for (int tt = 0; tt < 25; tt++) {
        const float4 wv = *(const float4*)&wS[tt][nl0];
#pragma unroll
        for (int j = 0; j < 4; j++) {
            const float2 zv = ((float2*)zT[24 + nl0 + j - tt])[lane];
            const float g = ((const float*)&wv)[j];
            A[j].x = fmaf(g, zv.x, A[j].x);
            A[j].y = fmaf(g, zv.y, A[j].y);
        }
    }

#pragma unroll
    for (int j = 0; j < 4; j++) {
        const int node = nodeBase + nl0 + j;
        const float2 zvi = ((float2*)zT[24 + nl0 + j])[lane];
        float2 o;
        o.x = A[j].x - zvi.x;
        o.y = A[j].y - zvi.y;
        ((float2*)(g_u + node * 64))[lane] = o;
    }
}

// ---------------- launch ----------------
extern "C" void kernel_launch(void* const* d_in, const int* in_sizes, int n_in,
                              void* d_out, int out_size) {
    const float* h        = (const float*)d_in[0];
    const float* fc_enc   = (const float*)d_in[1];
    const float* diff_enc = (const float*)d_in[2];
    const float* att_enc  = (const float*)d_in[3];
    const float* fc_dec   = (const float*)d_in[4];
    const float* diff_dec = (const float*)d_in[5];
    const float* att_dec  = (const float*)d_in[6];
    const float* att_comb = (const float*)d_in[7];
    float* out = (float*)d_out;

    cudaFuncSetAttribute(gemm_tc<0>, cudaFuncAttributeMaxDynamicSharedMemorySize, GSMEM);
    cudaFuncSetAttribute(gemm_tc<1>, cudaFuncAttributeMaxDynamicSharedMemorySize, GSMEM);

    const int gemmBlocks = (NN + 127) / 128;   // 157

    gemm_tc<0><<<gemmBlocks, 256, GSMEM>>>(h, fc_enc, diff_enc, nullptr);
    enc_agg<<<NN / 32, 256>>>(att_enc, att_comb);
    dec_agg<<<NN / 32, 256>>>(diff_dec, att_dec);
    gemm_tc<1><<<gemmBlocks, 256, GSMEM>>>(nullptr, fc_dec, diff_dec, out);
}

// round 9
// speedup vs baseline: 1.1026x; 1.1026x over previous
#include <cuda_runtime.h>
#include <cstdint>

#define NN 20000

// ---------------- device scratch ----------------
__device__ float g_z1 [NN * 64];
__device__ float g_hd1[NN * 64];
__device__ float g_zc [NN * 64];
__device__ float g_u  [NN * 64];

// ---------------- helpers ----------------
__device__ __forceinline__ float warpSumAll(float v) {
#pragma unroll
    for (int o = 16; o > 0; o >>= 1) v += __shfl_xor_sync(0xffffffffu, v, o);
    return v;
}
__device__ __forceinline__ float warpMaxAll(float v) {
#pragma unroll
    for (int o = 16; o > 0; o >>= 1) v = fmaxf(v, __shfl_xor_sync(0xffffffffu, v, o));
    return v;
}
__device__ __forceinline__ float lrelu(float x) { return x > 0.f ? x : 0.01f * x; }
__device__ __forceinline__ float eluf(float x) {
    if (x > 0.f) return x;
    if (x > -0.25f)
        return x * (1.f + x * (0.5f + x * (0.16666667f + x * 0.041666667f)));
    return __expf(x) - 1.f;
}

union F2U { float2 f; unsigned long long u; };
__device__ __forceinline__ void fma2(float2& c, float2 a, float2 b) {
    F2U A, B, C; A.f = a; B.f = b; C.f = c;
    asm("fma.rn.f32x2 %0, %1, %2, %0;" : "+l"(C.u) : "l"(A.u), "l"(B.u));
    c = C.f;
}

// =====================================================================
// Classic register-tiled FFMA2 GEMM.
// Tile: 64 nodes (M) x 128 outs (N), K=128 in 8 chunks of 16. grid=313.
// 256 threads: tx = t&15 (N), ty = t>>4 (M). Thread tile 4 rows x 8 cols.
// As2[k][m] holds (a,a) float2 (pre-duplicated): LDS.128 -> 2 FFMA2-ready
// operands, zero splats. Bs[k][n] plain floats: LDS.128 -> 2 col-pairs.
// Per thread per k: 4 LDS.128 + 16 FFMA2  ->  FMA-bound ~4:1 over crossbar.
// DEC=0: C = h @ [fcE;dfE]^T  -> g_z1 (cols 0-63) / g_hd1 (cols 64-127)
// DEC=1: C = [zc|u] @ [fcD|diffD]^T -> Oout
// =====================================================================
template <int DEC>
__global__ __launch_bounds__(256, 2)
void gemm_f32(const float* __restrict__ Ain, const float* __restrict__ W0,
              const float* __restrict__ W1, float* __restrict__ Oout) {
    __shared__ __align__(16) float2 As2[16][66];   // [k][m] duplicated
    __shared__ __align__(16) float  Bs[16][132];   // [k][n]

    const int t = threadIdx.x;
    const int tx = t & 15, ty = t >> 4;
    const int node0 = blockIdx.x * 64;
    const int c0 = 4 * tx, c1 = 64 + 4 * tx;

    float2 acc[4][4];
#pragma unroll
    for (int i = 0; i < 4; i++)
#pragma unroll
        for (int j = 0; j < 4; j++) acc[i][j] = make_float2(0.f, 0.f);

#pragma unroll 1
    for (int ch = 0; ch < 8; ch++) {
        const int kk = ch * 16;

        // stage A chunk: As2[k][m] = dup(A[node0+m][kk+k])
#pragma unroll
        for (int i = t; i < 16 * 64; i += 256) {
            const int k = i & 15, m = i >> 4;
            const int node = node0 + m;
            float v;
            if (DEC) v = (node < NN) ? ((kk < 64) ? g_zc[node * 64 + kk + k]
                                                  : g_u [node * 64 + kk + k - 64]) : 0.f;
            else     v = (node < NN) ? Ain[node * 128 + kk + k] : 0.f;
            As2[k][m] = make_float2(v, v);
        }
        // stage B chunk: Bs[k][n] = W[n][kk+k]
#pragma unroll
        for (int i = t; i < 16 * 128; i += 256) {
            const int k = i & 15, n = i >> 4;
            float v;
            if (DEC) v = (kk < 64) ? W0[n * 64 + kk + k] : W1[n * 64 + kk + k - 64];
            else     v = (n < 64) ? W0[n * 128 + kk + k] : W1[(n - 64) * 128 + kk + k];
            Bs[k][n] = v;
        }
        __syncthreads();

#pragma unroll
        for (int k = 0; k < 16; k++) {
            float2 a[4], b[4];
            {
                const float4 t0 = *(const float4*)&As2[k][4 * ty];
                const float4 t1 = *(const float4*)&As2[k][4 * ty + 2];
                a[0] = make_float2(t0.x, t0.y); a[1] = make_float2(t0.z, t0.w);
                a[2] = make_float2(t1.x, t1.y); a[3] = make_float2(t1.z, t1.w);
            }
            {
                const float4 t0 = *(const float4*)&Bs[k][c0];
                const float4 t1 = *(const float4*)&Bs[k][c1];
                b[0] = make_float2(t0.x, t0.y); b[1] = make_float2(t0.z, t0.w);
                b[2] = make_float2(t1.x, t1.y); b[3] = make_float2(t1.z, t1.w);
            }
#pragma unroll
            for (int i = 0; i < 4; i++)
#pragma unroll
                for (int j = 0; j < 4; j++) fma2(acc[i][j], a[i], b[j]);
        }
        __syncthreads();
    }

    // epilogue
#pragma unroll
    for (int i = 0; i < 4; i++) {
        const int node = node0 + 4 * ty + i;
        if (node >= NN) break;
        float4 lo = make_float4(acc[i][0].x, acc[i][0].y, acc[i][1].x, acc[i][1].y);
        float4 hi = make_float4(acc[i][2].x, acc[i][2].y, acc[i][3].x, acc[i][3].y);
        if (DEC) {
            *(float4*)(Oout + node * 128 + c0) = lo;
            *(float4*)(Oout + node * 128 + c1) = hi;
        } else {
            *(float4*)(g_z1  + node * 64 + c0) = lo;   // cols 0-63
            *(float4*)(g_hd1 + node * 64 + c0) = hi;   // cols 64-127
        }
    }
}

// ---------------- encoder aggregation: 3 hops + hop-attention combine ----------------
__global__ __launch_bounds__(256) void enc_agg(const float* __restrict__ attE,
                                               const float* __restrict__ attC) {
    __shared__ __align__(16) float hdT[56][66];
    __shared__ float sT[56];
    __shared__ __align__(16) float wS[3][25][36];
    __shared__ float sAe[64], sAc[64];

    const int t = threadIdx.x, w = t >> 5, lane = t & 31;
    const int nodeBase = blockIdx.x * 32;
    const int nl0 = w * 4;

    if (t < 64) { sAe[t] = attE[t]; sAc[t] = attC[t]; }

    for (int r = w; r < 56; r += 8) {
        int g = nodeBase - 24 + r;
        if (g < 0) g += NN;
        ((float2*)hdT[r])[lane] = ((const float2*)(g_hd1 + g * 64))[lane];
    }
    __syncthreads();

    for (int r = w; r < 56; r += 8) {
        float2 hv = ((float2*)hdT[r])[lane];
        float p = warpSumAll(hv.x * sAe[2 * lane] + hv.y * sAe[2 * lane + 1]);
        if (lane == 0) sT[r] = p;
    }
    __syncthreads();

#pragma unroll
    for (int j = 0; j < 4; j++) {
        const int li = 24 + nl0 + j;
        const float s_i = sT[li];
        float el = (lane < 25) ? lrelu(sT[li - lane] - s_i) : -1e30f;
        const float m1 = warpMaxAll(lane < 9  ? el : -1e30f);
        const float m2 = warpMaxAll(lane < 17 ? el : -1e30f);
        const float m3 = warpMaxAll(el);
        const float ex1 = (lane < 9)  ? __expf(el - m1) : 0.f;
        const float ex2 = (lane < 17) ? __expf(el - m2) : 0.f;
        const float ex3 = (lane < 25) ? __expf(el - m3) : 0.f;
        const float r1 = 1.f / warpSumAll(ex1);
        const float r2 = 1.f / warpSumAll(ex2);
        const float r3 = 1.f / warpSumAll(ex3);
        if (lane < 25) {
            wS[0][lane][nl0 + j] = ex1 * r1;
            wS[1][lane][nl0 + j] = ex2 * r2;
            wS[2][lane][nl0 + j] = ex3 * r3;
        }
    }
    __syncwarp();

    float2 A[4][3];
#pragma unroll
    for (int j = 0; j < 4; j++)
#pragma unroll
        for (int hh = 0; hh < 3; hh++) A[j][hh] = make_float2(0.f, 0.f);

#pragma unroll
    for (int tt = 0; tt < 25; tt++) {
        const float4 w3 = *(const float4*)&wS[2][tt][nl0];
        float4 w2, w1;
        if (tt < 17) w2 = *(const float4*)&wS[1][tt][nl0];
        if (tt < 9)  w1 = *(const float4*)&wS[0][tt][nl0];
#pragma unroll
        for (int j = 0; j < 4; j++) {
            const float2 hv = ((float2*)hdT[24 + nl0 + j - tt])[lane];
            const float g3 = ((const float*)&w3)[j];
            A[j][2].x = fmaf(g3, hv.x, A[j][2].x);
            A[j][2].y = fmaf(g3, hv.y, A[j][2].y);
            if (tt < 17) {
                const float g2 = ((const float*)&w2)[j];
                A[j][1].x = fmaf(g2, hv.x, A[j][1].x);
                A[j][1].y = fmaf(g2, hv.y, A[j][1].y);
            }
            if (tt < 9) {
                const float g1 = ((const float*)&w1)[j];
                A[j][0].x = fmaf(g1, hv.x, A[j][0].x);
                A[j][0].y = fmaf(g1, hv.y, A[j][0].y);
            }
        }
    }

    const float ac0 = sAc[2 * lane], ac1 = sAc[2 * lane + 1];
#pragma unroll
    for (int j = 0; j < 4; j++) {
        const int li = 24 + nl0 + j;
        const int node = nodeBase + nl0 + j;
        const float2 hvi = ((float2*)hdT[li])[lane];
        const float2 zv  = ((const float2*)(g_z1 + node * 64))[lane];
        float2 Z1, Z2, Z3;
        Z1.x = eluf(zv.x + A[j][0].x - hvi.x); Z1.y = eluf(zv.y + A[j][0].y - hvi.y);
        Z2.x = eluf(zv.x + A[j][1].x - hvi.x); Z2.y = eluf(zv.y + A[j][1].y - hvi.y);
        Z3.x = eluf(zv.x + A[j][2].x - hvi.x); Z3.y = eluf(zv.y + A[j][2].y - hvi.y);

        const float c1 = warpSumAll(Z1.x * ac0 + Z1.y * ac1);
        const float c2 = warpSumAll(Z2.x * ac0 + Z2.y * ac1);
        const float c3 = warpSumAll(Z3.x * ac0 + Z3.y * ac1);
        const float l1 = lrelu(c1), l2 = lrelu(c2), l3 = lrelu(c3);
        const float mx = fmaxf(l1, fmaxf(l2, l3));
        const float e1 = __expf(l1 - mx), e2 = __expf(l2 - mx), e3 = __expf(l3 - mx);
        const float rd = 1.f / (e1 + e2 + e3);

        float2 o;
        o.x = (e1 * Z1.x + e2 * Z2.x + e3 * Z3.x) * rd;
        o.y = (e1 * Z1.y + e2 * Z2.y + e3 * Z3.y) * rd;
        ((float2*)(g_zc + node * 64))[lane] = o;
    }
}

// ---------------- decoder aggregation in 64-dim latent ----------------
__global__ __launch_bounds__(256) void dec_agg(const float* __restrict__ diffD,
                                               const float* __restrict__ attD) {
    __shared__ __align__(16) float zT[56][66];
    __shared__ float sT[56];
    __shared__ __align__(16) float wS[25][36];
    __shared__ float sv[64];

    const int t = threadIdx.x, w = t >> 5, lane = t & 31;
    const int nodeBase = blockIdx.x * 32;
    const int nl0 = w * 4;

    if (t < 64) {
        float a = 0.f;
#pragma unroll 4
        for (int od = 0; od < 128; od++) a = fmaf(diffD[od * 64 + t], attD[od], a);
        sv[t] = a;
    }

    for (int r = w; r < 56; r += 8) {
        int g = nodeBase - 24 + r;
        if (g < 0) g += NN;
        ((float2*)zT[r])[lane] = ((const float2*)(g_zc + g * 64))[lane];
    }
    __syncthreads();

    for (int r = w; r < 56; r += 8) {
        float2 zv = ((float2*)zT[r])[lane];
        float p = warpSumAll(zv.x * sv[2 * lane] + zv.y * sv[2 * lane + 1]);
        if (lane == 0) sT[r] = p;
    }
    __syncthreads();

#pragma unroll
    for (int j = 0; j < 4; j++) {
        const int li = 24 + nl0 + j;
        const float s_i = sT[li];
        float el = (lane < 25) ? lrelu(sT[li - lane] - s_i) : -1e30f;
        const float m = warpMaxAll(el);
        const float ex = (lane < 25) ? __expf(el - m) : 0.f;
        const float rd = 1.f / warpSumAll(ex);
        if (lane < 25) wS[lane][nl0 + j] = ex * rd;
    }
    __syncwarp();

    float2 A[4];
#pragma unroll
    for (int j = 0; j < 4; j++) A[j] = make_float2(0.f, 0.f);

#pragma unroll
    for (int tt = 0; tt < 25; tt++) {
        const float4 wv = *(const float4*)&wS[tt][nl0];
#pragma unroll
        for (int j = 0; j < 4; j++) {
            const float2 zv = ((float2*)zT[24 + nl0 + j - tt])[lane];
            const float g = ((const float*)&wv)[j];
            A[j].x = fmaf(g, zv.x, A[j].x);
            A[j].y = fmaf(g, zv.y, A[j].y);
        }
    }

#pragma unroll
    for (int j = 0; j < 4; j++) {
        const int node = nodeBase + nl0 + j;
        const float2 zvi = ((float2*)zT[24 + nl0 + j])[lane];
        float2 o;
        o.x = A[j].x - zvi.x;
        o.y = A[j].y - zvi.y;
        ((float2*)(g_u + node * 64))[lane] = o;
    }
}

// ---------------- launch ----------------
extern "C" void kernel_launch(void* const* d_in, const int* in_sizes, int n_in,
                              void* d_out, int out_size) {
    const float* h        = (const float*)d_in[0];
    const float* fc_enc   = (const float*)d_in[1];
    const float* diff_enc = (const float*)d_in[2];
    const float* att_enc  = (const float*)d_in[3];
    const float* fc_dec   = (const float*)d_in[4];
    const float* diff_dec = (const float*)d_in[5];
    const float* att_dec  = (const float*)d_in[6];
    const float* att_comb = (const float*)d_in[7];
    float* out = (float*)d_out;

    const int gemmBlocks = (NN + 63) / 64;   // 313

    gemm_f32<0><<<gemmBlocks, 256>>>(h, fc_enc, diff_enc, nullptr);
    enc_agg<<<NN / 32, 256>>>(att_enc, att_comb);
    dec_agg<<<NN / 32, 256>>>(diff_dec, att_dec);
    gemm_f32<1><<<gemmBlocks, 256>>>(nullptr, fc_dec, diff_dec, out);
}

// round 11
// speedup vs baseline: 1.1432x; 1.0368x over previous
#include <cuda_runtime.h>
#include <cstdint>

#define NN 20000

// ---------------- device scratch ----------------
__device__ float g_z1 [NN * 64];
__device__ float g_hd1[NN * 64];
__device__ float g_zc [NN * 64];
__device__ float g_u  [NN * 64];

// ---------------- helpers ----------------
__device__ __forceinline__ float warpSumAll(float v) {
#pragma unroll
    for (int o = 16; o > 0; o >>= 1) v += __shfl_xor_sync(0xffffffffu, v, o);
    return v;
}
__device__ __forceinline__ float warpMaxAll(float v) {
#pragma unroll
    for (int o = 16; o > 0; o >>= 1) v = fmaxf(v, __shfl_xor_sync(0xffffffffu, v, o));
    return v;
}
__device__ __forceinline__ float lrelu(float x) { return x > 0.f ? x : 0.01f * x; }
__device__ __forceinline__ float eluf(float x) {
    if (x > 0.f) return x;
    if (x > -0.25f)
        return x * (1.f + x * (0.5f + x * (0.16666667f + x * 0.041666667f)));
    return __expf(x) - 1.f;
}

union F2U { float2 f; unsigned long long u; };
__device__ __forceinline__ void fma2(float2& c, float2 a, float2 b) {
    F2U A, B, C; A.f = a; B.f = b; C.f = c;
    asm("fma.rn.f32x2 %0, %1, %2, %0;" : "+l"(C.u) : "l"(A.u), "l"(B.u));
    c = C.f;
}

// =====================================================================
// One-wave register-tiled FFMA2 GEMM.
// Tile: 72 nodes x 128 outs, K=128. Block = 288 thr. Grid = 278 <= 296
// (= 148 SMs x 2 blocks) -> SINGLE WAVE, no quantization tail.
// W resident in smem (staged once, ALL 128 k-rows); A double-buffered in
// 16-k chunks with LDG prefetch overlapped with compute.
// Inner loop indexes Bs with GLOBAL k = ch*16 + k  (R10 bug fixed).
// =====================================================================
static constexpr int MT    = 72;                 // nodes per block
static constexpr int NTHR  = 4 * MT;             // 288
static constexpr int BPITCH = 132;               // Bs row pitch (floats)
static constexpr int APITCH = MT + 2;            // As2 row pitch (float2)
static constexpr int BS_ELEMS = 128 * BPITCH;    // 16896 floats
static constexpr int AS_ELEMS = 2 * 16 * APITCH; // float2 count (2 buffers)
static constexpr int GSMEM = BS_ELEMS * 4 + AS_ELEMS * 8;  // 86528 bytes

template <int DEC>
__device__ __forceinline__ float loadA(const float* __restrict__ Ain, int node, int kg) {
    if (node >= NN) return 0.f;
    if (DEC) return (kg < 64) ? g_zc[node * 64 + kg] : g_u[node * 64 + kg - 64];
    return Ain[node * 128 + kg];
}

template <int DEC>
__global__ __launch_bounds__(NTHR, 2)
void gemm_f32(const float* __restrict__ Ain, const float* __restrict__ W0,
              const float* __restrict__ W1, float* __restrict__ Oout) {
    extern __shared__ __align__(16) float smem[];
    float*  Bs  = smem;                         // [128][BPITCH]
    float2* As2 = (float2*)(smem + BS_ELEMS);   // 2 x [16][APITCH]

    const int t = threadIdx.x;
    const int tx = t & 15, ty = t >> 4;         // ty in 0..17
    const int node0 = blockIdx.x * MT;
    const int c0 = 4 * tx, c1 = 64 + 4 * tx;

    // ---- stage full W once: Bs[k][n] = W[n][k] ----
    for (int i = t; i < 128 * 128; i += NTHR) {
        const int n = i >> 7, k = i & 127;
        float v;
        if (DEC) v = (k < 64) ? W0[n * 64 + k] : W1[n * 64 + k - 64];
        else     v = (n < 64) ? W0[n * 128 + k] : W1[(n - 64) * 128 + k];
        Bs[k * BPITCH + n] = v;
    }

    // ---- stage A chunk 0 ----
    float pf[4];
#pragma unroll
    for (int j = 0; j < 4; j++) {
        const int i = t + j * NTHR;             // < 16*MT = 1152
        pf[j] = loadA<DEC>(Ain, node0 + (i >> 4), i & 15);
    }
#pragma unroll
    for (int j = 0; j < 4; j++) {
        const int i = t + j * NTHR;
        As2[(i & 15) * APITCH + (i >> 4)] = make_float2(pf[j], pf[j]);
    }
    __syncthreads();

    float2 acc[4][4];
#pragma unroll
    for (int i = 0; i < 4; i++)
#pragma unroll
        for (int j = 0; j < 4; j++) acc[i][j] = make_float2(0.f, 0.f);

#pragma unroll 1
    for (int ch = 0; ch < 8; ch++) {
        // prefetch next chunk (overlaps with compute below)
        if (ch < 7) {
#pragma unroll
            for (int j = 0; j < 4; j++) {
                const int i = t + j * NTHR;
                pf[j] = loadA<DEC>(Ain, node0 + (i >> 4), (ch + 1) * 16 + (i & 15));
            }
        }

        const float2* Ab = As2 + (ch & 1) * 16 * APITCH;
        const float*  Bb = Bs + ch * 16 * BPITCH;      // GLOBAL k base (bug fix)
#pragma unroll
        for (int k = 0; k < 16; k++) {
            float2 a[4], b[4];
            {
                const float4 t0 = *(const float4*)&Ab[k * APITCH + 4 * ty];
                const float4 t1 = *(const float4*)&Ab[k * APITCH + 4 * ty + 2];
                a[0] = make_float2(t0.x, t0.y); a[1] = make_float2(t0.z, t0.w);
                a[2] = make_float2(t1.x, t1.y); a[3] = make_float2(t1.z, t1.w);
            }
            {
                const float4 t0 = *(const float4*)&Bb[k * BPITCH + c0];
                const float4 t1 = *(const float4*)&Bb[k * BPITCH + c1];
                b[0] = make_float2(t0.x, t0.y); b[1] = make_float2(t0.z, t0.w);
                b[2] = make_float2(t1.x, t1.y); b[3] = make_float2(t1.z, t1.w);
            }
#pragma unroll
            for (int i = 0; i < 4; i++)
#pragma unroll
                for (int j = 0; j < 4; j++) fma2(acc[i][j], a[i], b[j]);
        }

        if (ch < 7) {
            float2* An = As2 + ((ch + 1) & 1) * 16 * APITCH;
#pragma unroll
            for (int j = 0; j < 4; j++) {
                const int i = t + j * NTHR;
                An[(i & 15) * APITCH + (i >> 4)] = make_float2(pf[j], pf[j]);
            }
            __syncthreads();
        }
    }

    // ---- epilogue ----
#pragma unroll
    for (int i = 0; i < 4; i++) {
        const int node = node0 + 4 * ty + i;
        if (node >= NN) break;
        float4 lo = make_float4(acc[i][0].x, acc[i][0].y, acc[i][1].x, acc[i][1].y);
        float4 hi = make_float4(acc[i][2].x, acc[i][2].y, acc[i][3].x, acc[i][3].y);
        if (DEC) {
            *(float4*)(Oout + node * 128 + c0) = lo;
            *(float4*)(Oout + node * 128 + c1) = hi;
        } else {
            *(float4*)(g_z1  + node * 64 + c0) = lo;
            *(float4*)(g_hd1 + node * 64 + c0) = hi;
        }
    }
}

// ---------------- encoder aggregation: 3 hops + hop-attention combine ----------------
__global__ __launch_bounds__(256) void enc_agg(const float* __restrict__ attE,
                                               const float* __restrict__ attC) {
    __shared__ __align__(16) float hdT[56][66];
    __shared__ float sT[56];
    __shared__ __align__(16) float wS[3][25][36];
    __shared__ float sAe[64], sAc[64];

    const int t = threadIdx.x, w = t >> 5, lane = t & 31;
    const int nodeBase = blockIdx.x * 32;
    const int nl0 = w * 4;

    if (t < 64) { sAe[t] = attE[t]; sAc[t] = attC[t]; }

    for (int r = w; r < 56; r += 8) {
        int g = nodeBase - 24 + r;
        if (g < 0) g += NN;
        ((float2*)hdT[r])[lane] = ((const float2*)(g_hd1 + g * 64))[lane];
    }
    __syncthreads();

    for (int r = w; r < 56; r += 8) {
        float2 hv = ((float2*)hdT[r])[lane];
        float p = warpSumAll(hv.x * sAe[2 * lane] + hv.y * sAe[2 * lane + 1]);
        if (lane == 0) sT[r] = p;
    }
    __syncthreads();

#pragma unroll
    for (int j = 0; j < 4; j++) {
        const int li = 24 + nl0 + j;
        const float s_i = sT[li];
        float el = (lane < 25) ? lrelu(sT[li - lane] - s_i) : -1e30f;
        const float m1 = warpMaxAll(lane < 9  ? el : -1e30f);
        const float m2 = warpMaxAll(lane < 17 ? el : -1e30f);
        const float m3 = warpMaxAll(el);
        const float ex1 = (lane < 9)  ? __expf(el - m1) : 0.f;
        const float ex2 = (lane < 17) ? __expf(el - m2) : 0.f;
        const float ex3 = (lane < 25) ? __expf(el - m3) : 0.f;
        const float r1 = 1.f / warpSumAll(ex1);
        const float r2 = 1.f / warpSumAll(ex2);
        const float r3 = 1.f / warpSumAll(ex3);
        if (lane < 25) {
            wS[0][lane][nl0 + j] = ex1 * r1;
            wS[1][lane][nl0 + j] = ex2 * r2;
            wS[2][lane][nl0 + j] = ex3 * r3;
        }
    }
    __syncwarp();

    float2 A[4][3];
#pragma unroll
    for (int j = 0; j < 4; j++)
#pragma unroll
        for (int hh = 0; hh < 3; hh++) A[j][hh] = make_float2(0.f, 0.f);

#pragma unroll
    for (int tt = 0; tt < 25; tt++) {
        const float4 w3 = *(const float4*)&wS[2][tt][nl0];
        float4 w2, w1;
        if (tt < 17) w2 = *(const float4*)&wS[1][tt][nl0];
        if (tt < 9)  w1 = *(const float4*)&wS[0][tt][nl0];
#pragma unroll
        for (int j = 0; j < 4; j++) {
            const float2 hv = ((float2*)hdT[24 + nl0 + j - tt])[lane];
            const float g3 = ((const float*)&w3)[j];
            A[j][2].x = fmaf(g3, hv.x, A[j][2].x);
            A[j][2].y = fmaf(g3, hv.y, A[j][2].y);
            if (tt < 17) {
                const float g2 = ((const float*)&w2)[j];
                A[j][1].x = fmaf(g2, hv.x, A[j][1].x);
                A[j][1].y = fmaf(g2, hv.y, A[j][1].y);
            }
            if (tt < 9) {
                const float g1 = ((const float*)&w1)[j];
                A[j][0].x = fmaf(g1, hv.x, A[j][0].x);
                A[j][0].y = fmaf(g1, hv.y, A[j][0].y);
            }
        }
    }

    const float ac0 = sAc[2 * lane], ac1 = sAc[2 * lane + 1];
#pragma unroll
    for (int j = 0; j < 4; j++) {
        const int li = 24 + nl0 + j;
        const int node = nodeBase + nl0 + j;
        const float2 hvi = ((float2*)hdT[li])[lane];
        const float2 zv  = ((const float2*)(g_z1 + node * 64))[lane];
        float2 Z1, Z2, Z3;
        Z1.x = eluf(zv.x + A[j][0].x - hvi.x); Z1.y = eluf(zv.y + A[j][0].y - hvi.y);
        Z2.x = eluf(zv.x + A[j][1].x - hvi.x); Z2.y = eluf(zv.y + A[j][1].y - hvi.y);
        Z3.x = eluf(zv.x + A[j][2].x - hvi.x); Z3.y = eluf(zv.y + A[j][2].y - hvi.y);

        const float c1 = warpSumAll(Z1.x * ac0 + Z1.y * ac1);
        const float c2 = warpSumAll(Z2.x * ac0 + Z2.y * ac1);
        const float c3 = warpSumAll(Z3.x * ac0 + Z3.y * ac1);
        const float l1 = lrelu(c1), l2 = lrelu(c2), l3 = lrelu(c3);
        const float mx = fmaxf(l1, fmaxf(l2, l3));
        const float e1 = __expf(l1 - mx), e2 = __expf(l2 - mx), e3 = __expf(l3 - mx);
        const float rd = 1.f / (e1 + e2 + e3);

        float2 o;
        o.x = (e1 * Z1.x + e2 * Z2.x + e3 * Z3.x) * rd;
        o.y = (e1 * Z1.y + e2 * Z2.y + e3 * Z3.y) * rd;
        ((float2*)(g_zc + node * 64))[lane] = o;
    }
}

// ---------------- decoder aggregation in 64-dim latent ----------------
__global__ __launch_bounds__(256) void dec_agg(const float* __restrict__ diffD,
                                               const float* __restrict__ attD) {
    __shared__ __align__(16) float zT[56][66];
    __shared__ float sT[56];
    __shared__ __align__(16) float wS[25][36];
    __shared__ float sv[64];

    const int t = threadIdx.x, w = t >> 5, lane = t & 31;
    const int nodeBase = blockIdx.x * 32;
    const int nl0 = w * 4;

    if (t < 64) {
        float a = 0.f;
#pragma unroll 4
        for (int od = 0; od < 128; od++) a = fmaf(diffD[od * 64 + t], attD[od], a);
        sv[t] = a;
    }

    for (int r = w; r < 56; r += 8) {
        int g = nodeBase - 24 + r;
        if (g < 0) g += NN;
        ((float2*)zT[r])[lane] = ((const float2*)(g_zc + g * 64))[lane];
    }
    __syncthreads();

    for (int r = w; r < 56; r += 8) {
        float2 zv = ((float2*)zT[r])[lane];
        float p = warpSumAll(zv.x * sv[2 * lane] + zv.y * sv[2 * lane + 1]);
        if (lane == 0) sT[r] = p;
    }
    __syncthreads();

#pragma unroll
    for (int j = 0; j < 4; j++) {
        const int li = 24 + nl0 + j;
        const float s_i = sT[li];
        float el = (lane < 25) ? lrelu(sT[li - lane] - s_i) : -1e30f;
        const float m = warpMaxAll(el);
        const float ex = (lane < 25) ? __expf(el - m) : 0.f;
        const float rd = 1.f / warpSumAll(ex);
        if (lane < 25) wS[lane][nl0 + j] = ex * rd;
    }
    __syncwarp();

    float2 A[4];
#pragma unroll
    for (int j = 0; j < 4; j++) A[j] = make_float2(0.f, 0.f);

#pragma unroll
    for (int tt = 0; tt < 25; tt++) {
        const float4 wv = *(const float4*)&wS[tt][nl0];
#pragma unroll
        for (int j = 0; j < 4; j++) {
            const float2 zv = ((float2*)zT[24 + nl0 + j - tt])[lane];
            const float g = ((const float*)&wv)[j];
            A[j].x = fmaf(g, zv.x, A[j].x);
            A[j].y = fmaf(g, zv.y, A[j].y);
        }
    }

#pragma unroll
    for (int j = 0; j < 4; j++) {
        const int node = nodeBase + nl0 + j;
        const float2 zvi = ((float2*)zT[24 + nl0 + j])[lane];
        float2 o;
        o.x = A[j].x - zvi.x;
        o.y = A[j].y - zvi.y;
        ((float2*)(g_u + node * 64))[lane] = o;
    }
}

// ---------------- launch ----------------
extern "C" void kernel_launch(void* const* d_in, const int* in_sizes, int n_in,
                              void* d_out, int out_size) {
    const float* h        = (const float*)d_in[0];
    const float* fc_enc   = (const float*)d_in[1];
    const float* diff_enc = (const float*)d_in[2];
    const float* att_enc  = (const float*)d_in[3];
    const float* fc_dec   = (const float*)d_in[4];
    const float* diff_dec = (const float*)d_in[5];
    const float* att_dec  = (const float*)d_in[6];
    const float* att_comb = (const float*)d_in[7];
    float* out = (float*)d_out;

    cudaFuncSetAttribute(gemm_f32<0>, cudaFuncAttributeMaxDynamicSharedMemorySize, GSMEM);
    cudaFuncSetAttribute(gemm_f32<1>, cudaFuncAttributeMaxDynamicSharedMemorySize, GSMEM);

    const int gemmBlocks = (NN + MT - 1) / MT;   // 278 <= 296 -> one wave

    gemm_f32<0><<<gemmBlocks, NTHR, GSMEM>>>(h, fc_enc, diff_enc, nullptr);
    enc_agg<<<NN / 32, 256>>>(att_enc, att_comb);
    dec_agg<<<NN / 32, 256>>>(diff_dec, att_dec);
    gemm_f32<1><<<gemmBlocks, NTHR, GSMEM>>>(nullptr, fc_dec, diff_dec, out);
}